// round 6
// baseline (speedup 1.0000x reference)
#include <cuda_runtime.h>
#include <cuda_bf16.h>
#include <math.h>
#include <stdint.h>

#define BATCH 32
#define LEN   2048
#define DIM   1024
#define M_TOT (BATCH * LEN)      // 65536
#define NCHUNKS 4                // 256-wide n chunks

// ---------------- scratch (static, no allocation) ----------------
__device__ float g_ht[BATCH * DIM];
__device__ float g_spart[NCHUNKS * M_TOT];
__device__ float g_wpart[16 * BATCH * DIM];
// Split-precision B operand: [split][n][k] bf16, B[n][k] = Wa[n][1024+k]
__device__ __nv_bfloat16 g_B[2][DIM][DIM];

// ---------------- helpers ----------------
__device__ __forceinline__ uint32_t smem_u32(const void* p) {
    uint32_t a;
    asm("{ .reg .u64 t; cvta.to.shared.u64 t, %1; cvt.u32.u64 %0, t; }" : "=r"(a) : "l"(p));
    return a;
}
__device__ __forceinline__ void cp_async16(uint32_t dst, const void* src) {
    asm volatile("cp.async.cg.shared.global [%0], [%1], 16;" :: "r"(dst), "l"(src));
}
#define CP_COMMIT() asm volatile("cp.async.commit_group;" ::: "memory")
#define CP_WAIT0()  asm volatile("cp.async.wait_group 0;" ::: "memory")

#define LDSM4(r, addr) \
    asm volatile("ldmatrix.sync.aligned.m8n8.x4.shared.b16 {%0,%1,%2,%3}, [%4];" \
        : "=r"((r)[0]), "=r"((r)[1]), "=r"((r)[2]), "=r"((r)[3]) : "r"(addr))

#define MMA16816(c, a, b0, b1) \
    asm volatile("mma.sync.aligned.m16n8k16.row.col.f32.bf16.bf16.f32 " \
        "{%0,%1,%2,%3}, {%4,%5,%6,%7}, {%8,%9}, {%0,%1,%2,%3};" \
        : "+f"((c)[0]), "+f"((c)[1]), "+f"((c)[2]), "+f"((c)[3]) \
        : "r"((a)[0]), "r"((a)[1]), "r"((a)[2]), "r"((a)[3]), "r"(b0), "r"(b1))

__device__ __forceinline__ uint32_t pack2bf(float v0, float v1) {
    uint32_t r;
    asm("cvt.rn.bf16x2.f32 %0, %1, %2;" : "=r"(r) : "f"(v1), "f"(v0));  // v0 -> low half
    return r;
}

// ---------------- Kernel A: ht_proj[b][k] = sum_d x[b][d] * Wa[k][d] ----------------
__global__ void __launch_bounds__(128) ht_kernel(const float* __restrict__ x,
                                                 const float* __restrict__ Wa) {
    int k = blockIdx.x * 128 + threadIdx.x;
    __shared__ float xs[32][128];
    float acc[32];
#pragma unroll
    for (int b = 0; b < 32; b++) acc[b] = 0.f;
    for (int d0 = 0; d0 < DIM; d0 += 128) {
        for (int i = threadIdx.x; i < 32 * 128; i += 128) {
            int bb = i >> 7, dd = i & 127;
            xs[bb][dd] = x[bb * DIM + d0 + dd];
        }
        __syncthreads();
        const float* wrow = Wa + (size_t)k * (2 * DIM) + d0;
#pragma unroll 4
        for (int dd = 0; dd < 128; dd++) {
            float w = wrow[dd];
#pragma unroll
            for (int b = 0; b < 32; b++) acc[b] += xs[b][dd] * w;
        }
        __syncthreads();
    }
#pragma unroll
    for (int b = 0; b < 32; b++) g_ht[b * DIM + k] = acc[b];
}

// ---------------- Kernel B0: split Wa_s -> g_B  (g_B[s][n][k] = Wa[n][1024+k]) ----------------
__global__ void __launch_bounds__(256) bprep_kernel(const float* __restrict__ Wa) {
    int idx = blockIdx.x * 256 + threadIdx.x;   // 524288 total
    int kp = idx & 511;                          // k pair index
    int n  = idx >> 9;                           // 0..1023
    float v0 = Wa[(size_t)n * 2048 + 1024 + 2 * kp];
    float v1 = Wa[(size_t)n * 2048 + 1024 + 2 * kp + 1];
    uint32_t ph = pack2bf(v0, v1);
    float h0 = __uint_as_float(ph << 16);
    float h1 = __uint_as_float(ph & 0xffff0000u);
    uint32_t pl = pack2bf(v0 - h0, v1 - h1);
    uint32_t* B32 = (uint32_t*)g_B;
    B32[(size_t)0 * 524288 + n * 512 + kp] = ph;
    B32[(size_t)1 * 524288 + n * 512 + kp] = pl;
}

// ---------------- Kernel B: mma.sync bf16x3 score GEMM + tanh + Va ----------------
// CTA: M=128, N=256, K=1024 in 16 steps of 64. 8 warps, warp tile 64x64.
#define RS      144          // padded smem row stride (bytes) for 64 bf16
#define OFF_AH  0
#define OFF_AL  18432
#define OFF_BH  36864
#define OFF_BL  73728
#define STAGE   110592
#define SM_HT   221184
#define SM_VA   222208
#define SM_RED  223232
#define SM_TOTAL 225280

__global__ void __launch_bounds__(256, 1) score_kernel(const float* __restrict__ ctx,
                                                       const float* __restrict__ Va) {
    extern __shared__ char smem[];
    const uint32_t sb = smem_u32(smem);
    const int tid  = threadIdx.x;
    const int lane = tid & 31;
    const int wid  = tid >> 5;
    const int wm   = wid >> 2;        // 0..1 (64 rows each)
    const int wn   = wid & 3;         // 0..3 (64 cols each)
    const int nch  = blockIdx.x;
    const int m0   = blockIdx.y * 128;
    const int n0   = nch * 256;
    const int b    = blockIdx.y >> 4;

    float* sht = (float*)(smem + SM_HT);
    float* sva = (float*)(smem + SM_VA);
    sht[tid] = g_ht[b * DIM + n0 + tid];
    sva[tid] = Va[n0 + tid];

    float acc[4][8][4];
#pragma unroll
    for (int i = 0; i < 4; i++)
#pragma unroll
        for (int j = 0; j < 8; j++)
#pragma unroll
            for (int r = 0; r < 4; r++) acc[i][j][r] = 0.f;

    // A path: LDG fp32 -> regs -> split bf16 -> STS. thread: row=tid>>1, k-half=(tid&1)*32
    const int arow = tid >> 1;
    const int ak   = (tid & 1) * 32;
    float4 ra[8];

    // B path: cp.async 16B chunks. thread: chunk=tid&7, rows (tid>>3) + 32*pass
    const int bc  = tid & 7;
    const int br0 = tid >> 3;

#define LDGA(kc_) do { \
    const float* ap_ = ctx + (size_t)(m0 + arow) * DIM + (kc_) * 64 + ak; \
    _Pragma("unroll") \
    for (int i = 0; i < 8; i++) ra[i] = *(const float4*)(ap_ + i * 4); \
} while (0)

#define CPB(kc_, buf_) do { \
    _Pragma("unroll") \
    for (int s = 0; s < 2; s++) { \
        uint32_t base_ = sb + (buf_) * STAGE + (s ? OFF_BL : OFF_BH); \
        _Pragma("unroll") \
        for (int pass = 0; pass < 8; pass++) { \
            int row_ = br0 + pass * 32; \
            cp_async16(base_ + row_ * RS + bc * 16, \
                       &g_B[s][n0 + row_][(kc_) * 64 + bc * 8]); \
        } \
    } \
} while (0)

#define STSA(buf_) do { \
    char* bp_ = smem + (buf_) * STAGE; \
    _Pragma("unroll") \
    for (int i = 0; i < 8; i++) { \
        float4 v = ra[i]; \
        uint32_t p0 = pack2bf(v.x, v.y); \
        float h0 = __uint_as_float(p0 << 16), h1 = __uint_as_float(p0 & 0xffff0000u); \
        uint32_t l0 = pack2bf(v.x - h0, v.y - h1); \
        uint32_t p1 = pack2bf(v.z, v.w); \
        float h2 = __uint_as_float(p1 << 16), h3 = __uint_as_float(p1 & 0xffff0000u); \
        uint32_t l1 = pack2bf(v.z - h2, v.w - h3); \
        uint32_t off_ = (uint32_t)(arow * RS + (ak + i * 4) * 2); \
        *(uint2*)(bp_ + OFF_AH + off_) = make_uint2(p0, p1); \
        *(uint2*)(bp_ + OFF_AL + off_) = make_uint2(l0, l1); \
    } \
} while (0)

    // ldmatrix per-thread address components
    const uint32_t aoff = (uint32_t)((wm * 64 + (lane & 15)) * RS + (lane >> 4) * 16);
    const uint32_t boff = (uint32_t)((wn * 64 + (lane & 7) + ((lane >> 4) & 1) * 8) * RS
                                     + ((lane >> 3) & 1) * 16);

    // prologue: fill stage 0
    CPB(0, 0); CP_COMMIT();
    LDGA(0);
    STSA(0);
    CP_WAIT0();
    __syncthreads();

#pragma unroll 1
    for (int kc = 0; kc < 16; kc++) {
        if (kc < 15) {
            CPB(kc + 1, (kc + 1) & 1);
            CP_COMMIT();
            LDGA(kc + 1);
        }
        const uint32_t bufb = sb + (uint32_t)(kc & 1) * STAGE;
        const uint32_t aAh = bufb + OFF_AH + aoff;
        const uint32_t aAl = bufb + OFF_AL + aoff;
        const uint32_t aBh = bufb + OFF_BH + boff;
        const uint32_t aBl = bufb + OFF_BL + boff;

#pragma unroll
        for (int ks = 0; ks < 4; ks++) {
            uint32_t ah[4][4], al[4][4];
#pragma unroll
            for (int mt = 0; mt < 4; mt++) {
                LDSM4(ah[mt], aAh + mt * (16 * RS) + ks * 32);
                LDSM4(al[mt], aAl + mt * (16 * RS) + ks * 32);
            }
#pragma unroll
            for (int p = 0; p < 4; p++) {
                uint32_t bh[4], bl[4];
                LDSM4(bh, aBh + p * (16 * RS) + ks * 32);
                LDSM4(bl, aBl + p * (16 * RS) + ks * 32);
#pragma unroll
                for (int mt = 0; mt < 4; mt++) {
                    MMA16816(acc[mt][2 * p],     ah[mt], bh[0], bh[1]);
                    MMA16816(acc[mt][2 * p],     ah[mt], bl[0], bl[1]);
                    MMA16816(acc[mt][2 * p],     al[mt], bh[0], bh[1]);
                    MMA16816(acc[mt][2 * p + 1], ah[mt], bh[2], bh[3]);
                    MMA16816(acc[mt][2 * p + 1], ah[mt], bl[2], bl[3]);
                    MMA16816(acc[mt][2 * p + 1], al[mt], bh[2], bh[3]);
                }
            }
        }
        if (kc < 15) {
            STSA((kc + 1) & 1);
            CP_WAIT0();
        }
        __syncthreads();
    }

    // ---- epilogue: tanh(D + ht) * Va, reduce over n ----
    float* red = (float*)(smem + SM_RED);   // [128][4]
    const int quad = lane >> 2, qlane = lane & 3;
#pragma unroll
    for (int mt = 0; mt < 4; mt++) {
#pragma unroll
        for (int h = 0; h < 2; h++) {
            float s = 0.f;
#pragma unroll
            for (int nt = 0; nt < 8; nt++) {
#pragma unroll
                for (int j = 0; j < 2; j++) {
                    int c = wn * 64 + nt * 8 + qlane * 2 + j;
                    float d = acc[mt][nt][h * 2 + j];
                    s += sva[c] * tanhf(d + sht[c]);
                }
            }
            s += __shfl_xor_sync(0xffffffffu, s, 1);
            s += __shfl_xor_sync(0xffffffffu, s, 2);
            if (qlane == 0) {
                int row = wm * 64 + mt * 16 + quad + h * 8;
                red[row * 4 + wn] = s;
            }
        }
    }
    __syncthreads();
    if (tid < 128) {
        float s = red[tid * 4] + red[tid * 4 + 1] + red[tid * 4 + 2] + red[tid * 4 + 3];
        g_spart[(size_t)nch * M_TOT + m0 + tid] = s;
    }
}

// ---------------- Kernel C: sum partials + softmax ----------------
__global__ void __launch_bounds__(256) softmax_kernel(float* __restrict__ out) {
    int b = blockIdx.x;
    int tid = threadIdx.x;
    float v[8];
    float mx = -1e30f;
#pragma unroll
    for (int i = 0; i < 8; i++) {
        int l = i * 256 + tid;
        float s = 0.f;
#pragma unroll
        for (int c = 0; c < NCHUNKS; c++) s += g_spart[(size_t)c * M_TOT + b * LEN + l];
        v[i] = s;
        mx = fmaxf(mx, s);
    }
    __shared__ float sm[256];
    sm[tid] = mx; __syncthreads();
    for (int off = 128; off > 0; off >>= 1) {
        if (tid < off) sm[tid] = fmaxf(sm[tid], sm[tid + off]);
        __syncthreads();
    }
    mx = sm[0];
    __syncthreads();
    float lsum = 0.f;
#pragma unroll
    for (int i = 0; i < 8; i++) { v[i] = expf(v[i] - mx); lsum += v[i]; }
    sm[tid] = lsum; __syncthreads();
    for (int off = 128; off > 0; off >>= 1) {
        if (tid < off) sm[tid] += sm[tid + off];
        __syncthreads();
    }
    float inv = 1.f / sm[0];
#pragma unroll
    for (int i = 0; i < 8; i++)
        out[BATCH * DIM + b * LEN + i * 256 + tid] = v[i] * inv;
}

// ---------------- Kernel D: partial weighted sums ----------------
__global__ void __launch_bounds__(256) wpart_kernel(const float* __restrict__ ctx,
                                                    const float* __restrict__ out) {
    int ls = blockIdx.x;
    int b  = blockIdx.y;
    int tid = threadIdx.x;
    const float* attn = out + BATCH * DIM + b * LEN + ls * 128;
    const float* cp   = ctx + ((size_t)b * LEN + ls * 128) * DIM + tid * 4;
    float4 acc = make_float4(0.f, 0.f, 0.f, 0.f);
    for (int l = 0; l < 128; l++) {
        float a = attn[l];
        float4 v = *(const float4*)(cp + (size_t)l * DIM);
        acc.x += a * v.x; acc.y += a * v.y;
        acc.z += a * v.z; acc.w += a * v.w;
    }
    *(float4*)(g_wpart + ((size_t)ls * BATCH + b) * DIM + tid * 4) = acc;
}

// ---------------- Kernel E: reduce weighted partials ----------------
__global__ void __launch_bounds__(256) wreduce_kernel(float* __restrict__ out) {
    int i = blockIdx.x * 256 + threadIdx.x;
    float s = 0.f;
#pragma unroll
    for (int ls = 0; ls < 16; ls++) s += g_wpart[ls * (BATCH * DIM) + i];
    out[i] = s;
}

// ---------------- launch ----------------
extern "C" void kernel_launch(void* const* d_in, const int* in_sizes, int n_in,
                              void* d_out, int out_size) {
    const float* x   = (const float*)d_in[0];
    const float* ctx = (const float*)d_in[1];
    const float* Wa  = (const float*)d_in[2];
    const float* Va  = (const float*)d_in[3];
    float* out = (float*)d_out;

    cudaFuncSetAttribute(score_kernel, cudaFuncAttributeMaxDynamicSharedMemorySize, SM_TOTAL);

    ht_kernel<<<8, 128>>>(x, Wa);
    bprep_kernel<<<2048, 256>>>(Wa);
    score_kernel<<<dim3(NCHUNKS, 512), 256, SM_TOTAL>>>(ctx, Va);
    softmax_kernel<<<BATCH, 256>>>(out);
    wpart_kernel<<<dim3(16, BATCH), 256>>>(ctx, out);
    wreduce_kernel<<<BATCH * DIM / 256, 256>>>(out);
}

// round 7
// speedup vs baseline: 1.0857x; 1.0857x over previous
#include <cuda_runtime.h>
#include <cuda_bf16.h>
#include <math.h>
#include <stdint.h>

#define BATCH 32
#define LEN   2048
#define DIM   1024
#define M_TOT (BATCH * LEN)      // 65536
#define NCHUNKS 4                // 256-wide n chunks

// ---------------- scratch (static, no allocation) ----------------
__device__ float g_ht[BATCH * DIM];
__device__ float g_spart[NCHUNKS * M_TOT];
__device__ float g_wpart[16 * BATCH * DIM];
// Split-precision B operand: [split][n][k] bf16, B[n][k] = Wa[n][1024+k]
__device__ __nv_bfloat16 g_B[2][DIM][DIM];

// ---------------- helpers ----------------
__device__ __forceinline__ uint32_t smem_u32(const void* p) {
    uint32_t a;
    asm("{ .reg .u64 t; cvta.to.shared.u64 t, %1; cvt.u32.u64 %0, t; }" : "=r"(a) : "l"(p));
    return a;
}
__device__ __forceinline__ void cp_async16(uint32_t dst, const void* src) {
    asm volatile("cp.async.cg.shared.global [%0], [%1], 16;" :: "r"(dst), "l"(src));
}
#define CP_COMMIT() asm volatile("cp.async.commit_group;" ::: "memory")
#define CP_WAIT0()  asm volatile("cp.async.wait_group 0;" ::: "memory")

#define LDSM4(r, addr) \
    asm volatile("ldmatrix.sync.aligned.m8n8.x4.shared.b16 {%0,%1,%2,%3}, [%4];" \
        : "=r"((r)[0]), "=r"((r)[1]), "=r"((r)[2]), "=r"((r)[3]) : "r"(addr))

#define MMA16816(c, a, b0, b1) \
    asm volatile("mma.sync.aligned.m16n8k16.row.col.f32.bf16.bf16.f32 " \
        "{%0,%1,%2,%3}, {%4,%5,%6,%7}, {%8,%9}, {%0,%1,%2,%3};" \
        : "+f"((c)[0]), "+f"((c)[1]), "+f"((c)[2]), "+f"((c)[3]) \
        : "r"((a)[0]), "r"((a)[1]), "r"((a)[2]), "r"((a)[3]), "r"(b0), "r"(b1))

__device__ __forceinline__ uint32_t pack2bf(float v0, float v1) {
    uint32_t r;
    asm("cvt.rn.bf16x2.f32 %0, %1, %2;" : "=r"(r) : "f"(v1), "f"(v0));  // v0 -> low half
    return r;
}

// ---------------- Kernel A: ht_proj[b][k] = sum_d x[b][d] * Wa[k][d] ----------------
__global__ void __launch_bounds__(128) ht_kernel(const float* __restrict__ x,
                                                 const float* __restrict__ Wa) {
    int k = blockIdx.x * 128 + threadIdx.x;
    __shared__ float xs[32][128];
    float acc[32];
#pragma unroll
    for (int b = 0; b < 32; b++) acc[b] = 0.f;
    for (int d0 = 0; d0 < DIM; d0 += 128) {
        for (int i = threadIdx.x; i < 32 * 128; i += 128) {
            int bb = i >> 7, dd = i & 127;
            xs[bb][dd] = x[bb * DIM + d0 + dd];
        }
        __syncthreads();
        const float* wrow = Wa + (size_t)k * (2 * DIM) + d0;
#pragma unroll 4
        for (int dd = 0; dd < 128; dd++) {
            float w = wrow[dd];
#pragma unroll
            for (int b = 0; b < 32; b++) acc[b] += xs[b][dd] * w;
        }
        __syncthreads();
    }
#pragma unroll
    for (int b = 0; b < 32; b++) g_ht[b * DIM + k] = acc[b];
}

// ---------------- Kernel B0: split Wa_s -> g_B  (g_B[s][n][k] = Wa[n][1024+k]) ----------------
__global__ void __launch_bounds__(256) bprep_kernel(const float* __restrict__ Wa) {
    int idx = blockIdx.x * 256 + threadIdx.x;   // 524288 total
    int kp = idx & 511;                          // k pair index
    int n  = idx >> 9;                           // 0..1023
    float v0 = Wa[(size_t)n * 2048 + 1024 + 2 * kp];
    float v1 = Wa[(size_t)n * 2048 + 1024 + 2 * kp + 1];
    uint32_t ph = pack2bf(v0, v1);
    float h0 = __uint_as_float(ph << 16);
    float h1 = __uint_as_float(ph & 0xffff0000u);
    uint32_t pl = pack2bf(v0 - h0, v1 - h1);
    uint32_t* B32 = (uint32_t*)g_B;
    B32[(size_t)0 * 524288 + n * 512 + kp] = ph;
    B32[(size_t)1 * 524288 + n * 512 + kp] = pl;
}

// ---------------- Kernel B: mma.sync bf16x3 score GEMM + tanh + Va ----------------
// CTA: M=128, N=256, K=1024 in 32 steps of 32. 16 warps, warp tile 32x64.
#define RS      80           // padded smem row stride (bytes) for 32 bf16
#define OFF_AH  0            // 128 rows
#define OFF_AL  10240
#define OFF_BH  20480        // 256 rows
#define OFF_BL  40960
#define STAGE   61440
#define SM_HT   122880
#define SM_VA   123904
#define SM_RED  124928
#define SM_TOTAL 126976

__global__ void __launch_bounds__(512, 1) score_kernel(const float* __restrict__ ctx,
                                                       const float* __restrict__ Va) {
    extern __shared__ char smem[];
    const uint32_t sb = smem_u32(smem);
    const int tid  = threadIdx.x;
    const int lane = tid & 31;
    const int wid  = tid >> 5;        // 0..15
    const int wm   = wid >> 2;        // 0..3 (32 rows each)
    const int wn   = wid & 3;         // 0..3 (64 cols each)
    const int nch  = blockIdx.x;
    const int m0   = blockIdx.y * 128;
    const int n0   = nch * 256;
    const int b    = blockIdx.y >> 4;

    float* sht = (float*)(smem + SM_HT);
    float* sva = (float*)(smem + SM_VA);
    if (tid < 256) {
        sht[tid] = g_ht[b * DIM + n0 + tid];
        sva[tid] = Va[n0 + tid];
    }

    float acc[2][8][4];
#pragma unroll
    for (int i = 0; i < 2; i++)
#pragma unroll
        for (int j = 0; j < 8; j++)
#pragma unroll
            for (int r = 0; r < 4; r++) acc[i][j][r] = 0.f;

    // A path: LDG fp32 -> regs -> split bf16 -> STS. thread: row=tid>>2, quad=tid&3
    const int arow = tid >> 2;
    const int ac   = tid & 3;
    float4 ra[2];

    // B path: cp.async. thread: row=tid>>1 (0..255), half=tid&1
    const int brow = tid >> 1;
    const int bh2  = tid & 1;

#define LDGA(kc_) do { \
    const float* ap_ = ctx + (size_t)(m0 + arow) * DIM + (kc_) * 32; \
    ra[0] = *(const float4*)(ap_ + ac * 4); \
    ra[1] = *(const float4*)(ap_ + (ac + 4) * 4); \
} while (0)

#define CPB(kc_, buf_) do { \
    _Pragma("unroll") \
    for (int s = 0; s < 2; s++) { \
        uint32_t base_ = sb + (buf_) * STAGE + (s ? OFF_BL : OFF_BH) + brow * RS; \
        _Pragma("unroll") \
        for (int i = 0; i < 2; i++) { \
            int c_ = bh2 * 2 + i; \
            cp_async16(base_ + c_ * 16, &g_B[s][n0 + brow][(kc_) * 32 + c_ * 8]); \
        } \
    } \
} while (0)

#define STSA(buf_) do { \
    char* bp_ = smem + (buf_) * STAGE; \
    _Pragma("unroll") \
    for (int i = 0; i < 2; i++) { \
        float4 v = ra[i]; \
        uint32_t p0 = pack2bf(v.x, v.y); \
        float h0 = __uint_as_float(p0 << 16), h1 = __uint_as_float(p0 & 0xffff0000u); \
        uint32_t l0 = pack2bf(v.x - h0, v.y - h1); \
        uint32_t p1 = pack2bf(v.z, v.w); \
        float h2 = __uint_as_float(p1 << 16), h3 = __uint_as_float(p1 & 0xffff0000u); \
        uint32_t l1 = pack2bf(v.z - h2, v.w - h3); \
        uint32_t off_ = (uint32_t)(arow * RS + (ac + i * 4) * 8); \
        *(uint2*)(bp_ + OFF_AH + off_) = make_uint2(p0, p1); \
        *(uint2*)(bp_ + OFF_AL + off_) = make_uint2(l0, l1); \
    } \
} while (0)

    // ldmatrix per-thread address components
    const uint32_t aoff = (uint32_t)((wm * 32 + (lane & 15)) * RS + (lane >> 4) * 16);
    const uint32_t boff = (uint32_t)((wn * 64 + (lane & 7) + ((lane >> 4) & 1) * 8) * RS
                                     + ((lane >> 3) & 1) * 16);

    // prologue: fill stage 0
    CPB(0, 0); CP_COMMIT();
    LDGA(0);
    STSA(0);
    CP_WAIT0();
    __syncthreads();

#pragma unroll 1
    for (int kc = 0; kc < 32; kc++) {
        if (kc < 31) {
            CPB(kc + 1, (kc + 1) & 1);
            CP_COMMIT();
            LDGA(kc + 1);
        }
        const uint32_t bufb = sb + (uint32_t)(kc & 1) * STAGE;
        const uint32_t aAh = bufb + OFF_AH + aoff;
        const uint32_t aAl = bufb + OFF_AL + aoff;
        const uint32_t aBh = bufb + OFF_BH + boff;
        const uint32_t aBl = bufb + OFF_BL + boff;

#pragma unroll
        for (int ks = 0; ks < 2; ks++) {
            uint32_t ah[2][4], al[2][4];
#pragma unroll
            for (int mt = 0; mt < 2; mt++) {
                LDSM4(ah[mt], aAh + mt * (16 * RS) + ks * 32);
                LDSM4(al[mt], aAl + mt * (16 * RS) + ks * 32);
            }
#pragma unroll
            for (int p = 0; p < 4; p++) {
                uint32_t bh[4], bl[4];
                LDSM4(bh, aBh + p * (16 * RS) + ks * 32);
                LDSM4(bl, aBl + p * (16 * RS) + ks * 32);
#pragma unroll
                for (int mt = 0; mt < 2; mt++) {
                    MMA16816(acc[mt][2 * p],     ah[mt], bh[0], bh[1]);
                    MMA16816(acc[mt][2 * p],     ah[mt], bl[0], bl[1]);
                    MMA16816(acc[mt][2 * p],     al[mt], bh[0], bh[1]);
                    MMA16816(acc[mt][2 * p + 1], ah[mt], bh[2], bh[3]);
                    MMA16816(acc[mt][2 * p + 1], ah[mt], bl[2], bl[3]);
                    MMA16816(acc[mt][2 * p + 1], al[mt], bh[2], bh[3]);
                }
            }
        }
        if (kc < 31) {
            STSA((kc + 1) & 1);
            CP_WAIT0();
        }
        __syncthreads();
    }

    // ---- epilogue: tanh(D + ht) * Va, reduce over n ----
    float* red = (float*)(smem + SM_RED);   // [128][4]
    const int quad = lane >> 2, qlane = lane & 3;
#pragma unroll
    for (int mt = 0; mt < 2; mt++) {
#pragma unroll
        for (int h = 0; h < 2; h++) {
            float s = 0.f;
#pragma unroll
            for (int nt = 0; nt < 8; nt++) {
#pragma unroll
                for (int j = 0; j < 2; j++) {
                    int c = wn * 64 + nt * 8 + qlane * 2 + j;
                    float d = acc[mt][nt][h * 2 + j];
                    s += sva[c] * tanhf(d + sht[c]);
                }
            }
            s += __shfl_xor_sync(0xffffffffu, s, 1);
            s += __shfl_xor_sync(0xffffffffu, s, 2);
            if (qlane == 0) {
                int row = wm * 32 + mt * 16 + quad + h * 8;
                red[row * 4 + wn] = s;
            }
        }
    }
    __syncthreads();
    if (tid < 128) {
        float s = red[tid * 4] + red[tid * 4 + 1] + red[tid * 4 + 2] + red[tid * 4 + 3];
        g_spart[(size_t)nch * M_TOT + m0 + tid] = s;
    }
}

// ---------------- Kernel C: sum partials + softmax ----------------
__global__ void __launch_bounds__(256) softmax_kernel(float* __restrict__ out) {
    int b = blockIdx.x;
    int tid = threadIdx.x;
    float v[8];
    float mx = -1e30f;
#pragma unroll
    for (int i = 0; i < 8; i++) {
        int l = i * 256 + tid;
        float s = 0.f;
#pragma unroll
        for (int c = 0; c < NCHUNKS; c++) s += g_spart[(size_t)c * M_TOT + b * LEN + l];
        v[i] = s;
        mx = fmaxf(mx, s);
    }
    __shared__ float sm[256];
    sm[tid] = mx; __syncthreads();
    for (int off = 128; off > 0; off >>= 1) {
        if (tid < off) sm[tid] = fmaxf(sm[tid], sm[tid + off]);
        __syncthreads();
    }
    mx = sm[0];
    __syncthreads();
    float lsum = 0.f;
#pragma unroll
    for (int i = 0; i < 8; i++) { v[i] = expf(v[i] - mx); lsum += v[i]; }
    sm[tid] = lsum; __syncthreads();
    for (int off = 128; off > 0; off >>= 1) {
        if (tid < off) sm[tid] += sm[tid + off];
        __syncthreads();
    }
    float inv = 1.f / sm[0];
#pragma unroll
    for (int i = 0; i < 8; i++)
        out[BATCH * DIM + b * LEN + i * 256 + tid] = v[i] * inv;
}

// ---------------- Kernel D: partial weighted sums ----------------
__global__ void __launch_bounds__(256) wpart_kernel(const float* __restrict__ ctx,
                                                    const float* __restrict__ out) {
    int ls = blockIdx.x;
    int b  = blockIdx.y;
    int tid = threadIdx.x;
    const float* attn = out + BATCH * DIM + b * LEN + ls * 128;
    const float* cp   = ctx + ((size_t)b * LEN + ls * 128) * DIM + tid * 4;
    float4 acc = make_float4(0.f, 0.f, 0.f, 0.f);
    for (int l = 0; l < 128; l++) {
        float a = attn[l];
        float4 v = *(const float4*)(cp + (size_t)l * DIM);
        acc.x += a * v.x; acc.y += a * v.y;
        acc.z += a * v.z; acc.w += a * v.w;
    }
    *(float4*)(g_wpart + ((size_t)ls * BATCH + b) * DIM + tid * 4) = acc;
}

// ---------------- Kernel E: reduce weighted partials ----------------
__global__ void __launch_bounds__(256) wreduce_kernel(float* __restrict__ out) {
    int i = blockIdx.x * 256 + threadIdx.x;
    float s = 0.f;
#pragma unroll
    for (int ls = 0; ls < 16; ls++) s += g_wpart[ls * (BATCH * DIM) + i];
    out[i] = s;
}

// ---------------- launch ----------------
extern "C" void kernel_launch(void* const* d_in, const int* in_sizes, int n_in,
                              void* d_out, int out_size) {
    const float* x   = (const float*)d_in[0];
    const float* ctx = (const float*)d_in[1];
    const float* Wa  = (const float*)d_in[2];
    const float* Va  = (const float*)d_in[3];
    float* out = (float*)d_out;

    cudaFuncSetAttribute(score_kernel, cudaFuncAttributeMaxDynamicSharedMemorySize, SM_TOTAL);

    ht_kernel<<<8, 128>>>(x, Wa);
    bprep_kernel<<<2048, 256>>>(Wa);
    score_kernel<<<dim3(NCHUNKS, 512), 512, SM_TOTAL>>>(ctx, Va);
    softmax_kernel<<<BATCH, 256>>>(out);
    wpart_kernel<<<dim3(16, BATCH), 256>>>(ctx, out);
    wreduce_kernel<<<BATCH * DIM / 256, 256>>>(out);
}

// round 8
// speedup vs baseline: 1.2010x; 1.1062x over previous
#include <cuda_runtime.h>
#include <cuda_bf16.h>
#include <math.h>
#include <stdint.h>

#define BATCH 32
#define LEN   2048
#define DIM   1024
#define M_TOT (BATCH * LEN)      // 65536
#define NCHUNKS 8

// ---------------- scratch (static, no allocation) ----------------
__device__ float g_ht[BATCH * DIM];
__device__ float g_spart[NCHUNKS * M_TOT];
__device__ float g_wpart[16 * BATCH * DIM];
// Split-precision B operand: [split][n][k] bf16, B[n][k] = Wa[n][1024+k]
__device__ __nv_bfloat16 g_B[2][DIM][DIM];

// ---------------- helpers ----------------
__device__ __forceinline__ uint32_t smem_u32(const void* p) {
    uint32_t a;
    asm("{ .reg .u64 t; cvta.to.shared.u64 t, %1; cvt.u32.u64 %0, t; }" : "=r"(a) : "l"(p));
    return a;
}
__device__ __forceinline__ void cp_async16(uint32_t dst, const void* src) {
    asm volatile("cp.async.cg.shared.global [%0], [%1], 16;" :: "r"(dst), "l"(src));
}
#define CP_COMMIT() asm volatile("cp.async.commit_group;" ::: "memory")
#define CP_WAIT0()  asm volatile("cp.async.wait_group 0;" ::: "memory")

#define LDSM4(r, addr) \
    asm volatile("ldmatrix.sync.aligned.m8n8.x4.shared.b16 {%0,%1,%2,%3}, [%4];" \
        : "=r"((r)[0]), "=r"((r)[1]), "=r"((r)[2]), "=r"((r)[3]) : "r"(addr))

#define MMA16816(c, a, b0, b1) \
    asm volatile("mma.sync.aligned.m16n8k16.row.col.f32.bf16.bf16.f32 " \
        "{%0,%1,%2,%3}, {%4,%5,%6,%7}, {%8,%9}, {%0,%1,%2,%3};" \
        : "+f"((c)[0]), "+f"((c)[1]), "+f"((c)[2]), "+f"((c)[3]) \
        : "r"((a)[0]), "r"((a)[1]), "r"((a)[2]), "r"((a)[3]), "r"(b0), "r"(b1))

__device__ __forceinline__ uint32_t pack2bf(float v0, float v1) {
    uint32_t r;
    asm("cvt.rn.bf16x2.f32 %0, %1, %2;" : "=r"(r) : "f"(v1), "f"(v0));  // v0 -> low half
    return r;
}

// ---------------- Kernel A: ht_proj[b][k] = sum_d x[b][d] * Wa[k][d] ----------------
__global__ void __launch_bounds__(128) ht_kernel(const float* __restrict__ x,
                                                 const float* __restrict__ Wa) {
    int k = blockIdx.x * 128 + threadIdx.x;
    __shared__ float xs[32][128];
    float acc[32];
#pragma unroll
    for (int b = 0; b < 32; b++) acc[b] = 0.f;
    for (int d0 = 0; d0 < DIM; d0 += 128) {
        for (int i = threadIdx.x; i < 32 * 128; i += 128) {
            int bb = i >> 7, dd = i & 127;
            xs[bb][dd] = x[bb * DIM + d0 + dd];
        }
        __syncthreads();
        const float* wrow = Wa + (size_t)k * (2 * DIM) + d0;
#pragma unroll 4
        for (int dd = 0; dd < 128; dd++) {
            float w = wrow[dd];
#pragma unroll
            for (int b = 0; b < 32; b++) acc[b] += xs[b][dd] * w;
        }
        __syncthreads();
    }
#pragma unroll
    for (int b = 0; b < 32; b++) g_ht[b * DIM + k] = acc[b];
}

// ---------------- Kernel B0: split Wa_s -> g_B  (g_B[s][n][k] = Wa[n][1024+k]) ----------------
__global__ void __launch_bounds__(256) bprep_kernel(const float* __restrict__ Wa) {
    int idx = blockIdx.x * 256 + threadIdx.x;   // 524288 total
    int kp = idx & 511;                          // k pair index
    int n  = idx >> 9;                           // 0..1023
    float v0 = Wa[(size_t)n * 2048 + 1024 + 2 * kp];
    float v1 = Wa[(size_t)n * 2048 + 1024 + 2 * kp + 1];
    uint32_t ph = pack2bf(v0, v1);
    float h0 = __uint_as_float(ph << 16);
    float h1 = __uint_as_float(ph & 0xffff0000u);
    uint32_t pl = pack2bf(v0 - h0, v1 - h1);
    uint32_t* B32 = (uint32_t*)g_B;
    B32[(size_t)0 * 524288 + n * 512 + kp] = ph;
    B32[(size_t)1 * 524288 + n * 512 + kp] = pl;
}

// ---------------- Kernel B: mma.sync bf16x3 score GEMM + tanh + Va ----------------
// CTA: M=128, N=128, K=1024 in 32 steps of 32. 8 warps, warp tile 64x32. 2 CTAs/SM.
#define RS      80          // padded smem row stride (bytes) for 32 bf16
#define OFF_AH  0
#define OFF_AL  10240
#define OFF_BH  20480
#define OFF_BL  30720
#define BUF_SZ  40960
#define SM_HT   81920
#define SM_VA   82432
#define SM_RED  82944
#define SM_TOTAL 84992

__global__ void __launch_bounds__(256, 2) score_kernel(const float* __restrict__ ctx,
                                                       const float* __restrict__ Va) {
    extern __shared__ char smem[];
    const uint32_t sb = smem_u32(smem);
    const int tid  = threadIdx.x;
    const int lane = tid & 31;
    const int wid  = tid >> 5;
    const int wm   = wid >> 2;        // 0..1 (64 rows each)
    const int wn   = wid & 3;         // 0..3 (32 cols each)
    const int nch  = blockIdx.x;
    const int m0   = blockIdx.y * 128;
    const int n0   = nch * 128;
    const int b    = blockIdx.y >> 4;

    float* sht = (float*)(smem + SM_HT);
    float* sva = (float*)(smem + SM_VA);
    if (tid < 128) {
        sht[tid] = g_ht[b * DIM + n0 + tid];
        sva[tid] = Va[n0 + tid];
    }

    float acc[4][4][4];
#pragma unroll
    for (int i = 0; i < 4; i++)
#pragma unroll
        for (int j = 0; j < 4; j++)
#pragma unroll
            for (int r = 0; r < 4; r++) acc[i][j][r] = 0.f;

    // A path: LDG fp32 -> regs -> split bf16 -> STS. thread: 8 threads/row
    const int t8 = tid & 7, rA0 = tid >> 3;
    float4 ra[4];

    // B path: cp.async. thread: row = tid>>1 (0..127), half = tid&1
    const int brow = tid >> 1;
    const int bh2  = tid & 1;

#define LDGA(kc_) do { \
    const float* ap_ = ctx + (size_t)(m0 + rA0) * DIM + (kc_) * 32 + t8 * 4; \
    _Pragma("unroll") \
    for (int rr = 0; rr < 4; rr++) ra[rr] = *(const float4*)(ap_ + (size_t)rr * 32 * DIM); \
} while (0)

#define CPB(kc_, buf_) do { \
    _Pragma("unroll") \
    for (int s = 0; s < 2; s++) { \
        uint32_t base_ = sb + (buf_) * BUF_SZ + (s ? OFF_BL : OFF_BH) + brow * RS; \
        _Pragma("unroll") \
        for (int i = 0; i < 2; i++) { \
            int c_ = bh2 * 2 + i; \
            cp_async16(base_ + c_ * 16, &g_B[s][n0 + brow][(kc_) * 32 + c_ * 8]); \
        } \
    } \
} while (0)

#define STSA(buf_) do { \
    char* bp_ = smem + (buf_) * BUF_SZ; \
    _Pragma("unroll") \
    for (int rr = 0; rr < 4; rr++) { \
        float4 v = ra[rr]; \
        uint32_t p0 = pack2bf(v.x, v.y); \
        float h0 = __uint_as_float(p0 << 16), h1 = __uint_as_float(p0 & 0xffff0000u); \
        uint32_t l0 = pack2bf(v.x - h0, v.y - h1); \
        uint32_t p1 = pack2bf(v.z, v.w); \
        float h2 = __uint_as_float(p1 << 16), h3 = __uint_as_float(p1 & 0xffff0000u); \
        uint32_t l1 = pack2bf(v.z - h2, v.w - h3); \
        int row = rA0 + rr * 32; \
        *(uint2*)(bp_ + OFF_AH + row * RS + t8 * 8) = make_uint2(p0, p1); \
        *(uint2*)(bp_ + OFF_AL + row * RS + t8 * 8) = make_uint2(l0, l1); \
    } \
} while (0)

    // ldmatrix per-thread address components
    const uint32_t aoff = (uint32_t)((wm * 64 + (lane & 15)) * RS + (lane >> 4) * 16);
    const uint32_t boff = (uint32_t)((wn * 32 + (lane & 7) + ((lane >> 4) & 1) * 8) * RS
                                     + ((lane >> 3) & 1) * 16);

    // prologue: fill stage 0
    CPB(0, 0); CP_COMMIT();
    LDGA(0);
    STSA(0);
    CP_WAIT0();
    __syncthreads();

#pragma unroll 1
    for (int kc = 0; kc < 32; kc++) {
        if (kc < 31) {
            CPB(kc + 1, (kc + 1) & 1);
            CP_COMMIT();
            LDGA(kc + 1);
        }
        const uint32_t bufb = sb + (uint32_t)(kc & 1) * BUF_SZ;
        const uint32_t aAh = bufb + OFF_AH + aoff;
        const uint32_t aAl = bufb + OFF_AL + aoff;
        const uint32_t aBh = bufb + OFF_BH + boff;
        const uint32_t aBl = bufb + OFF_BL + boff;

#pragma unroll
        for (int ks = 0; ks < 2; ks++) {
            uint32_t bh[2][4], bl[2][4];
#pragma unroll
            for (int p = 0; p < 2; p++) {
                LDSM4(bh[p], aBh + p * (16 * RS) + ks * 32);
                LDSM4(bl[p], aBl + p * (16 * RS) + ks * 32);
            }
#pragma unroll
            for (int mt = 0; mt < 4; mt++) {
                uint32_t ah[4], al[4];
                LDSM4(ah, aAh + mt * (16 * RS) + ks * 32);
                LDSM4(al, aAl + mt * (16 * RS) + ks * 32);
#pragma unroll
                for (int nt = 0; nt < 4; nt++) {
                    uint32_t* bhp = &bh[nt >> 1][(nt & 1) * 2];
                    uint32_t* blp = &bl[nt >> 1][(nt & 1) * 2];
                    MMA16816(acc[mt][nt], ah, bhp[0], bhp[1]);
                    MMA16816(acc[mt][nt], ah, blp[0], blp[1]);
                    MMA16816(acc[mt][nt], al, bhp[0], bhp[1]);
                }
            }
        }
        if (kc < 31) {
            STSA((kc + 1) & 1);
            CP_WAIT0();
        }
        __syncthreads();
    }

    // ---- epilogue: tanh(D + ht) * Va, reduce over n ----
    float* red = (float*)(smem + SM_RED);   // [128][4]
    const int quad = lane >> 2, qlane = lane & 3;
#pragma unroll
    for (int mt = 0; mt < 4; mt++) {
#pragma unroll
        for (int h = 0; h < 2; h++) {
            float s = 0.f;
#pragma unroll
            for (int nt = 0; nt < 4; nt++) {
#pragma unroll
                for (int j = 0; j < 2; j++) {
                    int c = wn * 32 + nt * 8 + qlane * 2 + j;
                    float d = acc[mt][nt][h * 2 + j];
                    s += sva[c] * tanhf(d + sht[c]);
                }
            }
            s += __shfl_xor_sync(0xffffffffu, s, 1);
            s += __shfl_xor_sync(0xffffffffu, s, 2);
            if (qlane == 0) {
                int row = wm * 64 + mt * 16 + quad + h * 8;
                red[row * 4 + wn] = s;
            }
        }
    }
    __syncthreads();
    if (tid < 128) {
        float s = red[tid * 4] + red[tid * 4 + 1] + red[tid * 4 + 2] + red[tid * 4 + 3];
        g_spart[(size_t)nch * M_TOT + m0 + tid] = s;
    }
}

// ---------------- Kernel C: sum partials + softmax ----------------
__global__ void __launch_bounds__(256) softmax_kernel(float* __restrict__ out) {
    int b = blockIdx.x;
    int tid = threadIdx.x;
    float v[8];
    float mx = -1e30f;
#pragma unroll
    for (int i = 0; i < 8; i++) {
        int l = i * 256 + tid;
        float s = 0.f;
#pragma unroll
        for (int c = 0; c < NCHUNKS; c++) s += g_spart[(size_t)c * M_TOT + b * LEN + l];
        v[i] = s;
        mx = fmaxf(mx, s);
    }
    __shared__ float sm[256];
    sm[tid] = mx; __syncthreads();
    for (int off = 128; off > 0; off >>= 1) {
        if (tid < off) sm[tid] = fmaxf(sm[tid], sm[tid + off]);
        __syncthreads();
    }
    mx = sm[0];
    __syncthreads();
    float lsum = 0.f;
#pragma unroll
    for (int i = 0; i < 8; i++) { v[i] = expf(v[i] - mx); lsum += v[i]; }
    sm[tid] = lsum; __syncthreads();
    for (int off = 128; off > 0; off >>= 1) {
        if (tid < off) sm[tid] += sm[tid + off];
        __syncthreads();
    }
    float inv = 1.f / sm[0];
#pragma unroll
    for (int i = 0; i < 8; i++)
        out[BATCH * DIM + b * LEN + i * 256 + tid] = v[i] * inv;
}

// ---------------- Kernel D: partial weighted sums ----------------
__global__ void __launch_bounds__(256) wpart_kernel(const float* __restrict__ ctx,
                                                    const float* __restrict__ out) {
    int ls = blockIdx.x;
    int b  = blockIdx.y;
    int tid = threadIdx.x;
    const float* attn = out + BATCH * DIM + b * LEN + ls * 128;
    const float* cp   = ctx + ((size_t)b * LEN + ls * 128) * DIM + tid * 4;
    float4 acc = make_float4(0.f, 0.f, 0.f, 0.f);
    for (int l = 0; l < 128; l++) {
        float a = attn[l];
        float4 v = *(const float4*)(cp + (size_t)l * DIM);
        acc.x += a * v.x; acc.y += a * v.y;
        acc.z += a * v.z; acc.w += a * v.w;
    }
    *(float4*)(g_wpart + ((size_t)ls * BATCH + b) * DIM + tid * 4) = acc;
}

// ---------------- Kernel E: reduce weighted partials ----------------
__global__ void __launch_bounds__(256) wreduce_kernel(float* __restrict__ out) {
    int i = blockIdx.x * 256 + threadIdx.x;
    float s = 0.f;
#pragma unroll
    for (int ls = 0; ls < 16; ls++) s += g_wpart[ls * (BATCH * DIM) + i];
    out[i] = s;
}

// ---------------- launch ----------------
extern "C" void kernel_launch(void* const* d_in, const int* in_sizes, int n_in,
                              void* d_out, int out_size) {
    const float* x   = (const float*)d_in[0];
    const float* ctx = (const float*)d_in[1];
    const float* Wa  = (const float*)d_in[2];
    const float* Va  = (const float*)d_in[3];
    float* out = (float*)d_out;

    cudaFuncSetAttribute(score_kernel, cudaFuncAttributeMaxDynamicSharedMemorySize, SM_TOTAL);

    ht_kernel<<<8, 128>>>(x, Wa);
    bprep_kernel<<<2048, 256>>>(Wa);
    score_kernel<<<dim3(NCHUNKS, 512), 256, SM_TOTAL>>>(ctx, Va);
    softmax_kernel<<<BATCH, 256>>>(out);
    wpart_kernel<<<dim3(16, BATCH), 256>>>(ctx, out);
    wreduce_kernel<<<BATCH * DIM / 256, 256>>>(out);
}

// round 9
// speedup vs baseline: 1.6649x; 1.3863x over previous
#include <cuda_runtime.h>
#include <cuda_bf16.h>
#include <cuda_fp16.h>
#include <math.h>
#include <stdint.h>

#define BATCH 32
#define LEN   2048
#define DIM   1024
#define M_TOT (BATCH * LEN)      // 65536
#define NCHUNKS 8

// ---------------- scratch (static, no allocation) ----------------
__device__ float g_ht[BATCH * DIM];
__device__ float g_spart[NCHUNKS * M_TOT];
__device__ float g_wpart[16 * BATCH * DIM];
// Split-precision B operand: [split][n][k] fp16, b = b_hi + b_lo, B[n][k] = Wa[n][1024+k]
__device__ __half g_B[2][DIM][DIM];

// ---------------- helpers ----------------
__device__ __forceinline__ uint32_t smem_u32(const void* p) {
    uint32_t a;
    asm("{ .reg .u64 t; cvta.to.shared.u64 t, %1; cvt.u32.u64 %0, t; }" : "=r"(a) : "l"(p));
    return a;
}
__device__ __forceinline__ void cp_async16(uint32_t dst, const void* src) {
    asm volatile("cp.async.cg.shared.global [%0], [%1], 16;" :: "r"(dst), "l"(src));
}
#define CP_COMMIT() asm volatile("cp.async.commit_group;" ::: "memory")
#define CP_WAIT0()  asm volatile("cp.async.wait_group 0;" ::: "memory")

#define LDSM4(r, addr) \
    asm volatile("ldmatrix.sync.aligned.m8n8.x4.shared.b16 {%0,%1,%2,%3}, [%4];" \
        : "=r"((r)[0]), "=r"((r)[1]), "=r"((r)[2]), "=r"((r)[3]) : "r"(addr))

#define MMAF16(c, a, b0, b1) \
    asm volatile("mma.sync.aligned.m16n8k16.row.col.f32.f16.f16.f32 " \
        "{%0,%1,%2,%3}, {%4,%5,%6,%7}, {%8,%9}, {%0,%1,%2,%3};" \
        : "+f"((c)[0]), "+f"((c)[1]), "+f"((c)[2]), "+f"((c)[3]) \
        : "r"((a)[0]), "r"((a)[1]), "r"((a)[2]), "r"((a)[3]), "r"(b0), "r"(b1))

__device__ __forceinline__ uint32_t pack2h(float v0, float v1) {
    uint32_t r;
    asm("cvt.rn.f16x2.f32 %0, %1, %2;" : "=r"(r) : "f"(v1), "f"(v0));  // v0 -> low half
    return r;
}

// ---------------- Kernel A: ht_proj[b][k] = sum_d x[b][d] * Wa[k][d] ----------------
// grid (8 k-tiles, 8 b-groups) x 128 threads
__global__ void __launch_bounds__(128) ht_kernel(const float* __restrict__ x,
                                                 const float* __restrict__ Wa) {
    int k = blockIdx.x * 128 + threadIdx.x;
    int bg = blockIdx.y * 4;
    __shared__ float xs[4][128];
    float acc[4];
#pragma unroll
    for (int b = 0; b < 4; b++) acc[b] = 0.f;
    for (int d0 = 0; d0 < DIM; d0 += 128) {
        for (int i = threadIdx.x; i < 4 * 128; i += 128) {
            int bb = i >> 7, dd = i & 127;
            xs[bb][dd] = x[(bg + bb) * DIM + d0 + dd];
        }
        __syncthreads();
        const float* wrow = Wa + (size_t)k * (2 * DIM) + d0;
#pragma unroll 8
        for (int dd = 0; dd < 128; dd++) {
            float w = wrow[dd];
#pragma unroll
            for (int b = 0; b < 4; b++) acc[b] += xs[b][dd] * w;
        }
        __syncthreads();
    }
#pragma unroll
    for (int b = 0; b < 4; b++) g_ht[(bg + b) * DIM + k] = acc[b];
}

// ---------------- Kernel B0: split Wa_s -> g_B (fp16 hi/lo) ----------------
__global__ void __launch_bounds__(256) bprep_kernel(const float* __restrict__ Wa) {
    int idx = blockIdx.x * 256 + threadIdx.x;   // 524288 total
    int kp = idx & 511;                          // k pair index
    int n  = idx >> 9;                           // 0..1023
    float v0 = Wa[(size_t)n * 2048 + 1024 + 2 * kp];
    float v1 = Wa[(size_t)n * 2048 + 1024 + 2 * kp + 1];
    __half h0 = __float2half_rn(v0);
    __half h1 = __float2half_rn(v1);
    __half l0 = __float2half_rn(v0 - __half2float(h0));
    __half l1 = __float2half_rn(v1 - __half2float(h1));
    __half2 ph = __halves2half2(h0, h1);
    __half2 pl = __halves2half2(l0, l1);
    uint32_t* B32 = (uint32_t*)g_B;
    B32[(size_t)0 * 524288 + n * 512 + kp] = *(uint32_t*)&ph;
    B32[(size_t)1 * 524288 + n * 512 + kp] = *(uint32_t*)&pl;
}

// ---------------- Kernel B: mma.sync fp16x2 score GEMM + tanh + Va ----------------
// CTA: M=128, N=128, K=1024 in 32 steps of 32. 8 warps, warp tile 64x32. 2 CTAs/SM.
#define RS      80          // padded smem row stride (bytes) for 32 fp16
#define OFF_A   0           // 128 rows x 80
#define OFF_BH  10240
#define OFF_BL  20480
#define BUF_SZ  30720
#define SM_HT   61440
#define SM_VA   61952
#define SM_RED  62464
#define SM_TOTAL 64512

__global__ void __launch_bounds__(256, 2) score_kernel(const float* __restrict__ ctx,
                                                       const float* __restrict__ Va) {
    extern __shared__ char smem[];
    const uint32_t sb = smem_u32(smem);
    const int tid  = threadIdx.x;
    const int lane = tid & 31;
    const int wid  = tid >> 5;
    const int wm   = wid >> 2;        // 0..1 (64 rows each)
    const int wn   = wid & 3;         // 0..3 (32 cols each)
    const int nch  = blockIdx.x;
    const int m0   = blockIdx.y * 128;
    const int n0   = nch * 128;
    const int b    = blockIdx.y >> 4;

    float* sht = (float*)(smem + SM_HT);
    float* sva = (float*)(smem + SM_VA);
    if (tid < 128) {
        sht[tid] = g_ht[b * DIM + n0 + tid];
        sva[tid] = Va[n0 + tid];
    }

    float acc[4][4][4];
#pragma unroll
    for (int i = 0; i < 4; i++)
#pragma unroll
        for (int j = 0; j < 4; j++)
#pragma unroll
            for (int r = 0; r < 4; r++) acc[i][j][r] = 0.f;

    // A path: LDG fp32 -> regs -> fp16 -> STS. 8 threads/row
    const int t8 = tid & 7, rA0 = tid >> 3;
    float4 ra[4];

    // B path: cp.async. thread: row = tid>>1 (0..127), half = tid&1
    const int brow = tid >> 1;
    const int bh2  = tid & 1;

#define LDGA(kc_) do { \
    const float* ap_ = ctx + (size_t)(m0 + rA0) * DIM + (kc_) * 32 + t8 * 4; \
    _Pragma("unroll") \
    for (int rr = 0; rr < 4; rr++) ra[rr] = *(const float4*)(ap_ + (size_t)rr * 32 * DIM); \
} while (0)

#define CPB(kc_, buf_) do { \
    _Pragma("unroll") \
    for (int s = 0; s < 2; s++) { \
        uint32_t base_ = sb + (buf_) * BUF_SZ + (s ? OFF_BL : OFF_BH) + brow * RS; \
        _Pragma("unroll") \
        for (int i = 0; i < 2; i++) { \
            int c_ = bh2 * 2 + i; \
            cp_async16(base_ + c_ * 16, &g_B[s][n0 + brow][(kc_) * 32 + c_ * 8]); \
        } \
    } \
} while (0)

#define STSA(buf_) do { \
    char* bp_ = smem + (buf_) * BUF_SZ; \
    _Pragma("unroll") \
    for (int rr = 0; rr < 4; rr++) { \
        float4 v = ra[rr]; \
        uint32_t p0 = pack2h(v.x, v.y); \
        uint32_t p1 = pack2h(v.z, v.w); \
        int row = rA0 + rr * 32; \
        *(uint2*)(bp_ + OFF_A + row * RS + t8 * 8) = make_uint2(p0, p1); \
    } \
} while (0)

    // ldmatrix per-thread address components
    const uint32_t aoff = (uint32_t)((wm * 64 + (lane & 15)) * RS + (lane >> 4) * 16);
    const uint32_t boff = (uint32_t)((wn * 32 + (lane & 7) + ((lane >> 4) & 1) * 8) * RS
                                     + ((lane >> 3) & 1) * 16);

    // prologue: fill stage 0
    CPB(0, 0); CP_COMMIT();
    LDGA(0);
    STSA(0);
    CP_WAIT0();
    __syncthreads();

#pragma unroll 1
    for (int kc = 0; kc < 32; kc++) {
        if (kc < 31) {
            CPB(kc + 1, (kc + 1) & 1);
            CP_COMMIT();
            LDGA(kc + 1);
        }
        const uint32_t bufb = sb + (uint32_t)(kc & 1) * BUF_SZ;
        const uint32_t aA  = bufb + OFF_A + aoff;
        const uint32_t aBh = bufb + OFF_BH + boff;
        const uint32_t aBl = bufb + OFF_BL + boff;

#pragma unroll
        for (int ks = 0; ks < 2; ks++) {
            uint32_t bh[2][4], bl[2][4];
#pragma unroll
            for (int p = 0; p < 2; p++) {
                LDSM4(bh[p], aBh + p * (16 * RS) + ks * 32);
                LDSM4(bl[p], aBl + p * (16 * RS) + ks * 32);
            }
#pragma unroll
            for (int mt = 0; mt < 4; mt++) {
                uint32_t ah[4];
                LDSM4(ah, aA + mt * (16 * RS) + ks * 32);
#pragma unroll
                for (int nt = 0; nt < 4; nt++) {
                    uint32_t* bhp = &bh[nt >> 1][(nt & 1) * 2];
                    uint32_t* blp = &bl[nt >> 1][(nt & 1) * 2];
                    MMAF16(acc[mt][nt], ah, bhp[0], bhp[1]);
                    MMAF16(acc[mt][nt], ah, blp[0], blp[1]);
                }
            }
        }
        if (kc < 31) {
            STSA((kc + 1) & 1);
            CP_WAIT0();
        }
        __syncthreads();
    }

    // ---- epilogue: tanh(D + ht) * Va, reduce over n ----
    float* red = (float*)(smem + SM_RED);   // [128][4]
    const int quad = lane >> 2, qlane = lane & 3;
#pragma unroll
    for (int mt = 0; mt < 4; mt++) {
#pragma unroll
        for (int h = 0; h < 2; h++) {
            float s = 0.f;
#pragma unroll
            for (int nt = 0; nt < 4; nt++) {
#pragma unroll
                for (int j = 0; j < 2; j++) {
                    int c = wn * 32 + nt * 8 + qlane * 2 + j;
                    float d = acc[mt][nt][h * 2 + j];
                    s += sva[c] * tanhf(d + sht[c]);
                }
            }
            s += __shfl_xor_sync(0xffffffffu, s, 1);
            s += __shfl_xor_sync(0xffffffffu, s, 2);
            if (qlane == 0) {
                int row = wm * 64 + mt * 16 + quad + h * 8;
                red[row * 4 + wn] = s;
            }
        }
    }
    __syncthreads();
    if (tid < 128) {
        float s = red[tid * 4] + red[tid * 4 + 1] + red[tid * 4 + 2] + red[tid * 4 + 3];
        g_spart[(size_t)nch * M_TOT + m0 + tid] = s;
    }
}

// ---------------- Kernel C: sum partials + softmax ----------------
__global__ void __launch_bounds__(256) softmax_kernel(float* __restrict__ out) {
    int b = blockIdx.x;
    int tid = threadIdx.x;
    float v[8];
    float mx = -1e30f;
#pragma unroll
    for (int i = 0; i < 8; i++) {
        int l = i * 256 + tid;
        float s = 0.f;
#pragma unroll
        for (int c = 0; c < NCHUNKS; c++) s += g_spart[(size_t)c * M_TOT + b * LEN + l];
        v[i] = s;
        mx = fmaxf(mx, s);
    }
    __shared__ float sm[256];
    sm[tid] = mx; __syncthreads();
    for (int off = 128; off > 0; off >>= 1) {
        if (tid < off) sm[tid] = fmaxf(sm[tid], sm[tid + off]);
        __syncthreads();
    }
    mx = sm[0];
    __syncthreads();
    float lsum = 0.f;
#pragma unroll
    for (int i = 0; i < 8; i++) { v[i] = expf(v[i] - mx); lsum += v[i]; }
    sm[tid] = lsum; __syncthreads();
    for (int off = 128; off > 0; off >>= 1) {
        if (tid < off) sm[tid] += sm[tid + off];
        __syncthreads();
    }
    float inv = 1.f / sm[0];
#pragma unroll
    for (int i = 0; i < 8; i++)
        out[BATCH * DIM + b * LEN + i * 256 + tid] = v[i] * inv;
}

// ---------------- Kernel D: partial weighted sums ----------------
__global__ void __launch_bounds__(256) wpart_kernel(const float* __restrict__ ctx,
                                                    const float* __restrict__ out) {
    int ls = blockIdx.x;
    int b  = blockIdx.y;
    int tid = threadIdx.x;
    const float* attn = out + BATCH * DIM + b * LEN + ls * 128;
    const float* cp   = ctx + ((size_t)b * LEN + ls * 128) * DIM + tid * 4;
    float4 acc = make_float4(0.f, 0.f, 0.f, 0.f);
    for (int l = 0; l < 128; l++) {
        float a = attn[l];
        float4 v = *(const float4*)(cp + (size_t)l * DIM);
        acc.x += a * v.x; acc.y += a * v.y;
        acc.z += a * v.z; acc.w += a * v.w;
    }
    *(float4*)(g_wpart + ((size_t)ls * BATCH + b) * DIM + tid * 4) = acc;
}

// ---------------- Kernel E: reduce weighted partials ----------------
__global__ void __launch_bounds__(256) wreduce_kernel(float* __restrict__ out) {
    int i = blockIdx.x * 256 + threadIdx.x;
    float s = 0.f;
#pragma unroll
    for (int ls = 0; ls < 16; ls++) s += g_wpart[ls * (BATCH * DIM) + i];
    out[i] = s;
}

// ---------------- launch ----------------
extern "C" void kernel_launch(void* const* d_in, const int* in_sizes, int n_in,
                              void* d_out, int out_size) {
    const float* x   = (const float*)d_in[0];
    const float* ctx = (const float*)d_in[1];
    const float* Wa  = (const float*)d_in[2];
    const float* Va  = (const float*)d_in[3];
    float* out = (float*)d_out;

    cudaFuncSetAttribute(score_kernel, cudaFuncAttributeMaxDynamicSharedMemorySize, SM_TOTAL);

    ht_kernel<<<dim3(8, 8), 128>>>(x, Wa);
    bprep_kernel<<<2048, 256>>>(Wa);
    score_kernel<<<dim3(NCHUNKS, 512), 256, SM_TOTAL>>>(ctx, Va);
    softmax_kernel<<<BATCH, 256>>>(out);
    wpart_kernel<<<dim3(16, BATCH), 256>>>(ctx, out);
    wreduce_kernel<<<BATCH * DIM / 256, 256>>>(out);
}

// round 11
// speedup vs baseline: 2.5559x; 1.5351x over previous
#include <cuda_runtime.h>
#include <cuda_bf16.h>
#include <cuda_fp16.h>
#include <math.h>
#include <stdint.h>

#define BATCH 32
#define LEN   2048
#define DIM   1024
#define M_TOT (BATCH * LEN)      // 65536
#define NCHUNKS 8

// ---------------- scratch (static, no allocation) ----------------
__device__ float g_ht[BATCH * DIM];
__device__ float g_spart[NCHUNKS * M_TOT];
__device__ float g_wpart[16 * BATCH * DIM];
// fp16 B operand: B[n][k] = Wa[n][1024+k]
__device__ __half g_B[DIM][DIM];

// ---------------- helpers ----------------
__device__ __forceinline__ uint32_t smem_u32(const void* p) {
    uint32_t a;
    asm("{ .reg .u64 t; cvta.to.shared.u64 t, %1; cvt.u32.u64 %0, t; }" : "=r"(a) : "l"(p));
    return a;
}
__device__ __forceinline__ void cp_async16(uint32_t dst, const void* src) {
    asm volatile("cp.async.cg.shared.global [%0], [%1], 16;" :: "r"(dst), "l"(src));
}
#define CP_COMMIT() asm volatile("cp.async.commit_group;" ::: "memory")
#define CP_WAIT0()  asm volatile("cp.async.wait_group 0;" ::: "memory")

#define LDSM4(r, addr) \
    asm volatile("ldmatrix.sync.aligned.m8n8.x4.shared.b16 {%0,%1,%2,%3}, [%4];" \
        : "=r"((r)[0]), "=r"((r)[1]), "=r"((r)[2]), "=r"((r)[3]) : "r"(addr))

#define MMAF16(c, a, b0, b1) \
    asm volatile("mma.sync.aligned.m16n8k16.row.col.f32.f16.f16.f32 " \
        "{%0,%1,%2,%3}, {%4,%5,%6,%7}, {%8,%9}, {%0,%1,%2,%3};" \
        : "+f"((c)[0]), "+f"((c)[1]), "+f"((c)[2]), "+f"((c)[3]) \
        : "r"((a)[0]), "r"((a)[1]), "r"((a)[2]), "r"((a)[3]), "r"(b0), "r"(b1))

__device__ __forceinline__ uint32_t pack2h(float v0, float v1) {
    uint32_t r;
    asm("cvt.rn.f16x2.f32 %0, %1, %2;" : "=r"(r) : "f"(v1), "f"(v0));  // v0 -> low half
    return r;
}

// ---------------- Kernel A: ht_proj[b][k] = sum_d x[b][d] * Wa[k][d] ----------------
__global__ void __launch_bounds__(128) ht_kernel(const float* __restrict__ x,
                                                 const float* __restrict__ Wa) {
    int k = blockIdx.x * 128 + threadIdx.x;
    int bg = blockIdx.y * 4;
    __shared__ float xs[4][128];
    float acc[4];
#pragma unroll
    for (int b = 0; b < 4; b++) acc[b] = 0.f;
    for (int d0 = 0; d0 < DIM; d0 += 128) {
        for (int i = threadIdx.x; i < 4 * 128; i += 128) {
            int bb = i >> 7, dd = i & 127;
            xs[bb][dd] = x[(bg + bb) * DIM + d0 + dd];
        }
        __syncthreads();
        const float* wrow = Wa + (size_t)k * (2 * DIM) + d0;
#pragma unroll 8
        for (int dd = 0; dd < 128; dd++) {
            float w = wrow[dd];
#pragma unroll
            for (int b = 0; b < 4; b++) acc[b] += xs[b][dd] * w;
        }
        __syncthreads();
    }
#pragma unroll
    for (int b = 0; b < 4; b++) g_ht[(bg + b) * DIM + k] = acc[b];
}

// ---------------- Kernel B0: convert Wa_s -> g_B (fp16) ----------------
__global__ void __launch_bounds__(256) bprep_kernel(const float* __restrict__ Wa) {
    int idx = blockIdx.x * 256 + threadIdx.x;   // 524288 total
    int kp = idx & 511;                          // k pair index
    int n  = idx >> 9;                           // 0..1023
    float v0 = Wa[(size_t)n * 2048 + 1024 + 2 * kp];
    float v1 = Wa[(size_t)n * 2048 + 1024 + 2 * kp + 1];
    ((uint32_t*)g_B)[n * 512 + kp] = pack2h(v0, v1);
}

// ---------------- Kernel B: mma.sync fp16 score GEMM + tanh + Va ----------------
// CTA: M=128, N=128, K=1024 in 32 steps of 32. 8 warps, warp tile 64x32. 2 CTAs/SM.
#define RS      80          // padded smem row stride (bytes) for 32 fp16
#define OFF_A   0           // 128 rows x 80
#define OFF_B   10240
#define BUF_SZ  20480
#define SM_HT   40960
#define SM_VA   41472
#define SM_RED  41984
#define SM_TOTAL 44032

__global__ void __launch_bounds__(256, 2) score_kernel(const float* __restrict__ ctx,
                                                       const float* __restrict__ Va) {
    extern __shared__ char smem[];
    const uint32_t sb = smem_u32(smem);
    const int tid  = threadIdx.x;
    const int lane = tid & 31;
    const int wid  = tid >> 5;
    const int wm   = wid >> 2;        // 0..1 (64 rows each)
    const int wn   = wid & 3;         // 0..3 (32 cols each)
    const int nch  = blockIdx.x;
    const int m0   = blockIdx.y * 128;
    const int n0   = nch * 128;
    const int b    = blockIdx.y >> 4;

    float* sht = (float*)(smem + SM_HT);
    float* sva = (float*)(smem + SM_VA);
    if (tid < 128) {
        sht[tid] = g_ht[b * DIM + n0 + tid];
        sva[tid] = Va[n0 + tid];
    }

    float acc[4][4][4];
#pragma unroll
    for (int i = 0; i < 4; i++)
#pragma unroll
        for (int j = 0; j < 4; j++)
#pragma unroll
            for (int r = 0; r < 4; r++) acc[i][j][r] = 0.f;

    // A path: LDG fp32 -> regs -> fp16 -> STS. 8 threads/row
    const int t8 = tid & 7, rA0 = tid >> 3;
    float4 ra[4];

    // B path: cp.async. thread: row = tid>>1 (0..127), half = tid&1
    const int brow = tid >> 1;
    const int bh2  = tid & 1;

#define LDGA(kc_) do { \
    const float* ap_ = ctx + (size_t)(m0 + rA0) * DIM + (kc_) * 32 + t8 * 4; \
    _Pragma("unroll") \
    for (int rr = 0; rr < 4; rr++) ra[rr] = *(const float4*)(ap_ + (size_t)rr * 32 * DIM); \
} while (0)

#define CPB(kc_, buf_) do { \
    uint32_t base_ = sb + (buf_) * BUF_SZ + OFF_B + brow * RS; \
    _Pragma("unroll") \
    for (int i = 0; i < 2; i++) { \
        int c_ = bh2 * 2 + i; \
        cp_async16(base_ + c_ * 16, &g_B[n0 + brow][(kc_) * 32 + c_ * 8]); \
    } \
} while (0)

#define STSA(buf_) do { \
    char* bp_ = smem + (buf_) * BUF_SZ; \
    _Pragma("unroll") \
    for (int rr = 0; rr < 4; rr++) { \
        float4 v = ra[rr]; \
        uint32_t p0 = pack2h(v.x, v.y); \
        uint32_t p1 = pack2h(v.z, v.w); \
        int row = rA0 + rr * 32; \
        *(uint2*)(bp_ + OFF_A + row * RS + t8 * 8) = make_uint2(p0, p1); \
    } \
} while (0)

    // ldmatrix per-thread address components
    const uint32_t aoff = (uint32_t)((wm * 64 + (lane & 15)) * RS + (lane >> 4) * 16);
    const uint32_t boff = (uint32_t)((wn * 32 + (lane & 7) + ((lane >> 4) & 1) * 8) * RS
                                     + ((lane >> 3) & 1) * 16);

    // prologue: fill stage 0
    CPB(0, 0); CP_COMMIT();
    LDGA(0);
    STSA(0);
    CP_WAIT0();
    __syncthreads();

#pragma unroll 1
    for (int kc = 0; kc < 32; kc++) {
        if (kc < 31) {
            CPB(kc + 1, (kc + 1) & 1);
            CP_COMMIT();
            LDGA(kc + 1);
        }
        const uint32_t bufb = sb + (uint32_t)(kc & 1) * BUF_SZ;
        const uint32_t aA = bufb + OFF_A + aoff;
        const uint32_t aB = bufb + OFF_B + boff;

#pragma unroll
        for (int ks = 0; ks < 2; ks++) {
            uint32_t bh[2][4];
#pragma unroll
            for (int p = 0; p < 2; p++) {
                LDSM4(bh[p], aB + p * (16 * RS) + ks * 32);
            }
#pragma unroll
            for (int mt = 0; mt < 4; mt++) {
                uint32_t ah[4];
                LDSM4(ah, aA + mt * (16 * RS) + ks * 32);
#pragma unroll
                for (int nt = 0; nt < 4; nt++) {
                    uint32_t* bhp = &bh[nt >> 1][(nt & 1) * 2];
                    MMAF16(acc[mt][nt], ah, bhp[0], bhp[1]);
                }
            }
        }
        if (kc < 31) {
            STSA((kc + 1) & 1);
            CP_WAIT0();
        }
        __syncthreads();
    }

    // ---- epilogue: tanh(D + ht) * Va, reduce over n ----
    float* red = (float*)(smem + SM_RED);   // [128][4]
    const int quad = lane >> 2, qlane = lane & 3;
#pragma unroll
    for (int mt = 0; mt < 4; mt++) {
#pragma unroll
        for (int h = 0; h < 2; h++) {
            float s = 0.f;
#pragma unroll
            for (int nt = 0; nt < 4; nt++) {
#pragma unroll
                for (int j = 0; j < 2; j++) {
                    int c = wn * 32 + nt * 8 + qlane * 2 + j;
                    float d = acc[mt][nt][h * 2 + j];
                    s += sva[c] * tanhf(d + sht[c]);
                }
            }
            s += __shfl_xor_sync(0xffffffffu, s, 1);
            s += __shfl_xor_sync(0xffffffffu, s, 2);
            if (qlane == 0) {
                int row = wm * 64 + mt * 16 + quad + h * 8;
                red[row * 4 + wn] = s;
            }
        }
    }
    __syncthreads();
    if (tid < 128) {
        float s = red[tid * 4] + red[tid * 4 + 1] + red[tid * 4 + 2] + red[tid * 4 + 3];
        g_spart[(size_t)nch * M_TOT + m0 + tid] = s;
    }
}

// ---------------- Kernel C: sum partials + softmax ----------------
__global__ void __launch_bounds__(256) softmax_kernel(float* __restrict__ out) {
    int b = blockIdx.x;
    int tid = threadIdx.x;
    float v[8];
    float mx = -1e30f;
#pragma unroll
    for (int i = 0; i < 8; i++) {
        int l = i * 256 + tid;
        float s = 0.f;
#pragma unroll
        for (int c = 0; c < NCHUNKS; c++) s += g_spart[(size_t)c * M_TOT + b * LEN + l];
        v[i] = s;
        mx = fmaxf(mx, s);
    }
    __shared__ float sm[256];
    sm[tid] = mx; __syncthreads();
    for (int off = 128; off > 0; off >>= 1) {
        if (tid < off) sm[tid] = fmaxf(sm[tid], sm[tid + off]);
        __syncthreads();
    }
    mx = sm[0];
    __syncthreads();
    float lsum = 0.f;
#pragma unroll
    for (int i = 0; i < 8; i++) { v[i] = expf(v[i] - mx); lsum += v[i]; }
    sm[tid] = lsum; __syncthreads();
    for (int off = 128; off > 0; off >>= 1) {
        if (tid < off) sm[tid] += sm[tid + off];
        __syncthreads();
    }
    float inv = 1.f / sm[0];
#pragma unroll
    for (int i = 0; i < 8; i++)
        out[BATCH * DIM + b * LEN + i * 256 + tid] = v[i] * inv;
}

// ---------------- Kernel D: partial weighted sums ----------------
__global__ void __launch_bounds__(256) wpart_kernel(const float* __restrict__ ctx,
                                                    const float* __restrict__ out) {
    int ls = blockIdx.x;
    int b  = blockIdx.y;
    int tid = threadIdx.x;
    const float* attn = out + BATCH * DIM + b * LEN + ls * 128;
    const float* cp   = ctx + ((size_t)b * LEN + ls * 128) * DIM + tid * 4;
    float4 acc = make_float4(0.f, 0.f, 0.f, 0.f);
    for (int l = 0; l < 128; l++) {
        float a = attn[l];
        float4 v = *(const float4*)(cp + (size_t)l * DIM);
        acc.x += a * v.x; acc.y += a * v.y;
        acc.z += a * v.z; acc.w += a * v.w;
    }
    *(float4*)(g_wpart + ((size_t)ls * BATCH + b) * DIM + tid * 4) = acc;
}

// ---------------- Kernel E: reduce weighted partials ----------------
__global__ void __launch_bounds__(256) wreduce_kernel(float* __restrict__ out) {
    int i = blockIdx.x * 256 + threadIdx.x;
    float s = 0.f;
#pragma unroll
    for (int ls = 0; ls < 16; ls++) s += g_wpart[ls * (BATCH * DIM) + i];
    out[i] = s;
}

// ---------------- launch ----------------
extern "C" void kernel_launch(void* const* d_in, const int* in_sizes, int n_in,
                              void* d_out, int out_size) {
    const float* x   = (const float*)d_in[0];
    const float* ctx = (const float*)d_in[1];
    const float* Wa  = (const float*)d_in[2];
    const float* Va  = (const float*)d_in[3];
    float* out = (float*)d_out;

    cudaFuncSetAttribute(score_kernel, cudaFuncAttributeMaxDynamicSharedMemorySize, SM_TOTAL);

    ht_kernel<<<dim3(8, 8), 128>>>(x, Wa);
    bprep_kernel<<<2048, 256>>>(Wa);
    score_kernel<<<dim3(NCHUNKS, 512), 256, SM_TOTAL>>>(ctx, Va);
    softmax_kernel<<<BATCH, 256>>>(out);
    wpart_kernel<<<dim3(16, BATCH), 256>>>(ctx, out);
    wreduce_kernel<<<BATCH * DIM / 256, 256>>>(out);
}